// round 4
// baseline (speedup 1.0000x reference)
#include <cuda_runtime.h>
#include <cfloat>
#include <cstdint>

#define BATCH 32
#define PTS   1024
#define KNN   20
#define NPTS  (BATCH*PTS)

// ---------------- device scratch (no allocations allowed) ----------------
__device__ int   g_idx1[NPTS*KNN];    // kNN in pos space
__device__ float g_x1  [NPTS*64];     // conv1 output
__device__ float g_x1sq[NPTS];        // |x1|^2 per point
__device__ int   g_idx2[NPTS*KNN];    // kNN in feature space
__device__ float g_z   [NPTS*128];    // x1_j @ Wb
__device__ float g_s   [NPTS*128];    // x1_i @ (Wt-Wb) + b
__device__ float g_x2  [NPTS*128];    // conv2 output

// packed fp32x2 fma (Blackwell FFMA2): d = a*b + c lane-wise
__device__ __forceinline__ float2 ffma2(float2 a, float2 b, float2 c){
    float2 d;
    asm("fma.rn.f32x2 %0, %1, %2, %3;"
        : "=l"(*(unsigned long long*)&d)
        : "l"(*(unsigned long long*)&a),
          "l"(*(unsigned long long*)&b),
          "l"(*(unsigned long long*)&c));
    return d;
}

// ordered-uint encoding for float atomicMax (handles negatives)
__device__ __forceinline__ unsigned f2key(float f){
    unsigned u = __float_as_uint(f);
    return (u & 0x80000000u) ? ~u : (u | 0x80000000u);
}
__device__ __forceinline__ float key2f(unsigned u){
    unsigned b = (u & 0x80000000u) ? (u & 0x7FFFFFFFu) : ~u;
    return __uint_as_float(b);
}

// ---------------- kernel 0/7: init + decode output ----------------
__global__ void init_out_kernel(unsigned* out){
    int t = blockIdx.x*blockDim.x + threadIdx.x;
    if (t < BATCH*128) out[t] = 0u;   // encodes -inf
}
__global__ void decode_out_kernel(unsigned* out){
    int t = blockIdx.x*blockDim.x + threadIdx.x;
    if (t < BATCH*128) out[t] = __float_as_uint(key2f(out[t]));
}

// ---------------- kernel 1: kNN in 3D position space (4-way j-split) ----------------
__global__ __launch_bounds__(128) void knn_pos_kernel(const float* __restrict__ pos){
    __shared__ float xs[PTS], ys[PTS], zs[PTS];
    __shared__ float mk[32*80];
    int cloud = blockIdx.y;
    int base  = cloud * PTS;
    int tid = threadIdx.x;
    for (int t = tid; t < PTS; t += 128){
        xs[t] = pos[(base+t)*3+0];
        ys[t] = pos[(base+t)*3+1];
        zs[t] = pos[(base+t)*3+2];
    }
    __syncthreads();
    int p = tid >> 2, s = tid & 3;
    int il = blockIdx.x*32 + p;
    float xi = xs[il], yi = ys[il], zi = zs[il];

    float bd[KNN]; int bj[KNN];
    #pragma unroll
    for (int k=0;k<KNN;k++){ bd[k]=FLT_MAX; bj[k]=base+il; }
    float worst = FLT_MAX; int wpos = 0;

    for (int j=s; j<PTS; j+=4){
        float dx = xs[j]-xi, dy = ys[j]-yi, dz = zs[j]-zi;
        float d  = dx*dx + dy*dy + dz*dz;
        if (d < worst){
            bd[wpos]=d; bj[wpos]=base+j;
            worst = bd[0]; wpos = 0;
            #pragma unroll
            for (int k=1;k<KNN;k++) if (bd[k] > worst){ worst = bd[k]; wpos = k; }
        }
    }
    int cb = p*80, myoff = s*20;
    #pragma unroll
    for (int k=0;k<KNN;k++) mk[cb+myoff+k]=bd[k];
    __syncthreads();
    int i = base + il;
    #pragma unroll
    for (int k=0;k<KNN;k++){
        float kc = bd[k]; int cpos = myoff + k;
        int rank = 0;
        for (int q=0;q<80;q++){
            float kq = mk[cb+q];
            rank += (kq < kc) || (kq == kc && q < cpos);
        }
        if (rank < KNN) g_idx1[i*KNN+rank] = bj[k];
    }
}

// ---------------- kernel 2: EdgeConv1 (warp per point, f32x2 layer 2) ----------------
__global__ __launch_bounds__(128) void conv1_kernel(
    const float* __restrict__ pos,
    const float* __restrict__ W1, const float* __restrict__ b1,
    const float* __restrict__ bns, const float* __restrict__ bnb,
    const float* __restrict__ W2, const float* __restrict__ b2)
{
    __shared__ float  sW1f[6*64];
    __shared__ float  sb1f[64];
    __shared__ float2 sW2p[32*64];   // [kpair][c] = {W2[2kp][c], W2[2kp+1][c]}
    __shared__ float  sb2[64];
    __shared__ float  sH[4][KNN*64];

    int tid = threadIdx.x;
    for (int t = tid; t < 64; t += 128){
        float sc = bns[t];
        sb1f[t] = b1[t]*sc + bnb[t];    // fold BN into layer-1 affine
        sb2[t]  = b2[t];
        #pragma unroll
        for (int d=0; d<6; d++) sW1f[d*64+t] = W1[d*64+t]*sc;
    }
    for (int t = tid; t < 2048; t += 128){
        int kp = t >> 6, c = t & 63;
        sW2p[t] = make_float2(W2[(2*kp)*64+c], W2[(2*kp+1)*64+c]);
    }
    __syncthreads();

    int warp = tid >> 5, lane = tid & 31;
    int i = blockIdx.x*4 + warp;
    float xi0 = pos[i*3+0], xi1 = pos[i*3+1], xi2 = pos[i*3+2];
    float* H = sH[warp];
    int c0 = lane, c1 = lane + 32;

    float w3a = sW1f[192+c0], w4a = sW1f[256+c0], w5a = sW1f[320+c0];
    float w3b = sW1f[192+c1], w4b = sW1f[256+c1], w5b = sW1f[320+c1];
    float basea = sb1f[c0] + xi0*sW1f[c0] + xi1*sW1f[64+c0] + xi2*sW1f[128+c0];
    float baseb = sb1f[c1] + xi0*sW1f[c1] + xi1*sW1f[64+c1] + xi2*sW1f[128+c1];

    // layer 1: per-edge hidden, relu, to shared
    #pragma unroll
    for (int j=0;j<KNN;j++){
        int n = g_idx1[i*KNN+j];
        float d0 = pos[n*3+0]-xi0, d1 = pos[n*3+1]-xi1, d2 = pos[n*3+2]-xi2;
        H[j*64+c0] = fmaxf(basea + d0*w3a + d1*w4a + d2*w5a, 0.f);
        H[j*64+c1] = fmaxf(baseb + d0*w3b + d1*w4b + d2*w5b, 0.f);
    }
    __syncwarp();

    // layer 2 with k-packed f32x2: acc halves = even/odd-k partial sums
    float sq = 0.f;
    #pragma unroll
    for (int p=0;p<2;p++){
        int c = lane + 32*p;
        float2 acc2[KNN];
        #pragma unroll
        for (int j=0;j<KNN;j++) acc2[j] = make_float2(0.f, 0.f);
        #pragma unroll 4
        for (int k4=0;k4<16;k4++){
            float2 q0 = sW2p[(2*k4)*64 + c];
            float2 q1 = sW2p[(2*k4+1)*64 + c];
            #pragma unroll
            for (int j=0;j<KNN;j++){
                float4 h4 = *(const float4*)&H[j*64 + 4*k4];
                const float2* hp = (const float2*)&h4;
                acc2[j] = ffma2(hp[0], q0, acc2[j]);
                acc2[j] = ffma2(hp[1], q1, acc2[j]);
            }
        }
        float m = -FLT_MAX;
        #pragma unroll
        for (int j=0;j<KNN;j++) m = fmaxf(m, acc2[j].x + acc2[j].y);
        m += sb2[c];                 // bias constant over j -> add after max
        g_x1[i*64+c] = m;
        sq += m*m;
    }
    #pragma unroll
    for (int o=16;o;o>>=1) sq += __shfl_xor_sync(0xffffffffu, sq, o);
    if (lane == 0) g_x1sq[i] = sq;
}

// ---------------- kernel 3: kNN in 64-d feature space — tiled GEMM + selection ----
// grid (8, 32), block 256 (16tx x 16ty), micro-tile 8x8, f32x2 k-packed.
#define KEY_STR 132
__global__ __launch_bounds__(256) void knn_feat_kernel(){
    extern __shared__ float sm[];
    float* sXi  = sm;                    // 128*64, XOR-swizzled float4 groups
    float* sXj  = sm + 8192;             // 128*64, same
    float* sKey = sm + 16384;            // 128*KEY_STR
    float* sSq  = sm + 16384 + 128*KEY_STR; // 128
    int cloud = blockIdx.y, base = cloud*PTS;
    int i0 = blockIdx.x*128;
    int tid = threadIdx.x;
    int tx = tid & 15, ty = tid >> 4;

    // load Xi tile once (swizzle float4 group: g ^= row>>3)
    for (int t = tid; t < 2048; t += 256){
        int row = t >> 4, g = t & 15;
        float4 v = *(const float4*)&g_x1[(base+i0+row)*64 + g*4];
        *(float4*)&sXi[row*64 + ((g ^ (row>>3))<<2)] = v;
    }

    int srow = tid >> 1, h = tid & 1;    // selection ownership: 2 threads/row
    float bd[KNN]; int bj[KNN];
    #pragma unroll
    for (int k=0;k<KNN;k++){ bd[k]=FLT_MAX; bj[k]=base+i0+srow; }
    float worst = FLT_MAX; int wpos = 0;

    for (int jt=0; jt<8; jt++){
        __syncthreads();
        for (int t = tid; t < 2048; t += 256){
            int row = t >> 4, g = t & 15;
            float4 v = *(const float4*)&g_x1[(base+jt*128+row)*64 + g*4];
            *(float4*)&sXj[row*64 + ((g ^ (row>>3))<<2)] = v;
        }
        if (tid < 128) sSq[tid] = g_x1sq[base + jt*128 + tid];
        __syncthreads();

        float2 acc[8][8];
        #pragma unroll
        for (int r=0;r<8;r++)
            #pragma unroll
            for (int c=0;c<8;c++) acc[r][c] = make_float2(0.f,0.f);

        #pragma unroll 4
        for (int k4=0;k4<16;k4++){
            int ao = ((k4 ^ ty) << 2), bo = ((k4 ^ tx) << 2);
            #pragma unroll
            for (int hf=0; hf<2; hf++){
                float2 a2[8], b2[8];
                #pragma unroll
                for (int r=0;r<8;r++) a2[r] = *(const float2*)&sXi[(ty*8+r)*64 + ao + 2*hf];
                #pragma unroll
                for (int c=0;c<8;c++) b2[c] = *(const float2*)&sXj[(tx*8+c)*64 + bo + 2*hf];
                #pragma unroll
                for (int r=0;r<8;r++)
                    #pragma unroll
                    for (int c=0;c<8;c++)
                        acc[r][c] = ffma2(a2[r], b2[c], acc[r][c]);
            }
        }

        // epilogue: key = sq[j] - 2*dot  -> sKey tile
        #pragma unroll
        for (int r=0;r<8;r++){
            int row = ty*8+r;
            #pragma unroll
            for (int c4=0;c4<2;c4++){
                float4 kv;
                float d0 = acc[r][c4*4+0].x + acc[r][c4*4+0].y;
                float d1 = acc[r][c4*4+1].x + acc[r][c4*4+1].y;
                float d2 = acc[r][c4*4+2].x + acc[r][c4*4+2].y;
                float d3 = acc[r][c4*4+3].x + acc[r][c4*4+3].y;
                kv.x = fmaf(-2.f, d0, sSq[tx*8 + c4*4+0]);
                kv.y = fmaf(-2.f, d1, sSq[tx*8 + c4*4+1]);
                kv.z = fmaf(-2.f, d2, sSq[tx*8 + c4*4+2]);
                kv.w = fmaf(-2.f, d3, sSq[tx*8 + c4*4+3]);
                *(float4*)&sKey[row*KEY_STR + tx*8 + c4*4] = kv;
            }
        }
        __syncthreads();

        // selection: thread scans 64 keys of its row-half
        const float* krow = &sKey[srow*KEY_STR + h*64];
        int jb = base + jt*128 + h*64;
        for (int c=0;c<64;c++){
            float key = krow[c];
            if (key < worst){
                bd[wpos]=key; bj[wpos]=jb+c;
                worst = bd[0]; wpos = 0;
                #pragma unroll
                for (int k=1;k<KNN;k++) if (bd[k] > worst){ worst = bd[k]; wpos = k; }
            }
        }
    }
    __syncthreads();
    // merge 2x20 candidates per row via rank (alias sKey)
    float* mk = sKey;                 // 128*40 floats
    int cb = srow*40, off = h*20;
    #pragma unroll
    for (int k=0;k<KNN;k++) mk[cb+off+k]=bd[k];
    __syncthreads();
    int i = base + i0 + srow;
    #pragma unroll
    for (int k=0;k<KNN;k++){
        float kc = bd[k]; int cpos = off + k;
        int rank = 0;
        for (int q=0;q<40;q++){
            float kq = mk[cb+q];
            rank += (kq < kc) || (kq == kc && q < cpos);
        }
        if (rank < KNN) g_idx2[i*KNN+rank] = bj[k];
    }
}

// ---------------- kernel 4: z = x1@Wb, s = x1@(Wt-Wb)+b (conv2 decomposed) ----------------
__global__ __launch_bounds__(256) void zs_kernel(const float* __restrict__ c2W,
                                                 const float* __restrict__ c2b){
    extern __shared__ float sm4[];
    float* sW = sm4;            // 128*128
    float* sx = sm4 + 16384;    // 8 warps * 2 pts * 64
    int tid = threadIdx.x, warp = tid>>5, lane = tid&31;
    for (int t=tid; t<16384; t+=256) sW[t] = c2W[t];
    __syncthreads();
    float cbv[4];
    #pragma unroll
    for (int q=0;q<4;q++) cbv[q] = c2b[lane+32*q];

    for (int g = blockIdx.x; g < NPTS/16; g += gridDim.x){
        int i0 = g*16 + warp*2;
        float* xw = sx + warp*128;
        xw[lane]      = g_x1[i0*64 + lane];
        xw[lane+32]   = g_x1[i0*64 + 32 + lane];
        xw[64+lane]   = g_x1[(i0+1)*64 + lane];
        xw[96+lane]   = g_x1[(i0+1)*64 + 32 + lane];
        __syncwarp();
        float az0[4]={0,0,0,0}, az1[4]={0,0,0,0}, at0[4]={0,0,0,0}, at1[4]={0,0,0,0};
        for (int k=0;k<64;k++){
            float x0 = xw[k], x1v = xw[64+k];
            #pragma unroll
            for (int q=0;q<4;q++){
                int c = lane + 32*q;
                float wt = sW[k*128+c];
                float wb = sW[(k+64)*128+c];
                at0[q] += x0*wt;  az0[q] += x0*wb;
                at1[q] += x1v*wt; az1[q] += x1v*wb;
            }
        }
        #pragma unroll
        for (int q=0;q<4;q++){
            int c = lane + 32*q;
            g_z[i0*128+c]     = az0[q];
            g_s[i0*128+c]     = at0[q]-az0[q]+cbv[q];
            g_z[(i0+1)*128+c] = az1[q];
            g_s[(i0+1)*128+c] = at1[q]-az1[q]+cbv[q];
        }
        __syncwarp();
    }
}

// ---------------- kernel 5: gather-max -> x2 ----------------
__global__ __launch_bounds__(256) void gather_kernel(){
    int gw   = (blockIdx.x*blockDim.x + threadIdx.x) >> 5;  // one warp per point
    int lane = threadIdx.x & 31;
    if (gw >= NPTS) return;
    const int* idx = &g_idx2[gw*KNN];
    float4 m = make_float4(-FLT_MAX,-FLT_MAX,-FLT_MAX,-FLT_MAX);
    #pragma unroll
    for (int j=0;j<KNN;j++){
        int n = idx[j];
        float4 v = *(const float4*)&g_z[n*128 + lane*4];
        m.x = fmaxf(m.x, v.x); m.y = fmaxf(m.y, v.y);
        m.z = fmaxf(m.z, v.z); m.w = fmaxf(m.w, v.w);
    }
    float4 sv = *(const float4*)&g_s[gw*128 + lane*4];
    float4 r  = make_float4(sv.x+m.x, sv.y+m.y, sv.z+m.z, sv.w+m.w);
    *(float4*)&g_x2[gw*128 + lane*4] = r;
}

// ---------------- kernel 6: lin([x1,x2]) + global max pool ----------------
__global__ __launch_bounds__(512) void linpool_kernel(const float* __restrict__ lW,
                                                      const float* __restrict__ lb,
                                                      unsigned* __restrict__ out){
    extern __shared__ float sm6[];
    float* sW = sm6;              // 192*128
    float* sx = sm6 + 192*128;    // 16 warps * 4 pts * 192
    int tid = threadIdx.x, warp = tid>>5, lane = tid&31;
    for (int t=tid; t<192*128; t+=512) sW[t] = lW[t];
    __syncthreads();
    float lbv[4];
    #pragma unroll
    for (int q=0;q<4;q++) lbv[q] = lb[lane+32*q];

    for (int ch = blockIdx.x*16 + warp; ch < NPTS/4; ch += gridDim.x*16){
        int p0 = ch*4;                   // 4 points, same cloud (4 | 1024)
        float* xw = sx + warp*4*192;
        #pragma unroll
        for (int pt=0; pt<4; pt++){
            int p = p0 + pt;
            #pragma unroll
            for (int t6=0; t6<6; t6++){
                int t = lane + t6*32;
                xw[pt*192 + t] = (t < 64) ? g_x1[p*64 + t] : g_x2[p*128 + (t-64)];
            }
        }
        __syncwarp();
        float acc[4][4];
        #pragma unroll
        for (int pt=0;pt<4;pt++)
            #pragma unroll
            for (int q=0;q<4;q++) acc[pt][q] = 0.f;
        #pragma unroll 4
        for (int k=0;k<192;k++){
            float w0 = sW[k*128+lane],    w1 = sW[k*128+lane+32];
            float w2 = sW[k*128+lane+64], w3 = sW[k*128+lane+96];
            #pragma unroll
            for (int pt=0;pt<4;pt++){
                float xv = xw[pt*192+k];
                acc[pt][0] += xv*w0; acc[pt][1] += xv*w1;
                acc[pt][2] += xv*w2; acc[pt][3] += xv*w3;
            }
        }
        int cloud = p0 >> 10;
        #pragma unroll
        for (int q=0;q<4;q++){
            float m = fmaxf(fmaxf(acc[0][q],acc[1][q]), fmaxf(acc[2][q],acc[3][q])) + lbv[q];
            atomicMax(&out[cloud*128 + lane + 32*q], f2key(m));
        }
        __syncwarp();
    }
}

// ---------------- launch ----------------
extern "C" void kernel_launch(void* const* d_in, const int* in_sizes, int n_in,
                              void* d_out, int out_size)
{
    const float* pos  = (const float*)d_in[0];
    const float* c1W1 = (const float*)d_in[2];
    const float* c1b1 = (const float*)d_in[3];
    const float* bns  = (const float*)d_in[4];
    const float* bnb  = (const float*)d_in[5];
    const float* c1W2 = (const float*)d_in[6];
    const float* c1b2 = (const float*)d_in[7];
    const float* c2W  = (const float*)d_in[8];
    const float* c2b  = (const float*)d_in[9];
    const float* lW   = (const float*)d_in[10];
    const float* lb   = (const float*)d_in[11];
    unsigned* out = (unsigned*)d_out;

    const int KF_SMEM = (16384 + 128*KEY_STR + 128) * 4;   // 133,632 B
    const int ZS_SMEM = (16384 + 8*128) * 4;               // 69,632 B
    const int LP_SMEM = (192*128 + 16*4*192) * 4;          // 147,456 B
    cudaFuncSetAttribute(knn_feat_kernel, cudaFuncAttributeMaxDynamicSharedMemorySize, KF_SMEM);
    cudaFuncSetAttribute(zs_kernel,       cudaFuncAttributeMaxDynamicSharedMemorySize, ZS_SMEM);
    cudaFuncSetAttribute(linpool_kernel,  cudaFuncAttributeMaxDynamicSharedMemorySize, LP_SMEM);

    init_out_kernel<<<16, 256>>>(out);
    knn_pos_kernel<<<dim3(PTS/32, BATCH), 128>>>(pos);
    conv1_kernel<<<NPTS/4, 128>>>(pos, c1W1, c1b1, bns, bnb, c1W2, c1b2);
    knn_feat_kernel<<<dim3(PTS/128, BATCH), 256, KF_SMEM>>>();
    zs_kernel<<<444, 256, ZS_SMEM>>>(c2W, c2b);
    gather_kernel<<<NPTS/8, 256>>>();
    linpool_kernel<<<148, 512, LP_SMEM>>>(lW, lb, out);
    decode_out_kernel<<<16, 256>>>(out);
}

// round 5
// speedup vs baseline: 1.4635x; 1.4635x over previous
#include <cuda_runtime.h>
#include <cfloat>
#include <cstdint>

#define BATCH 32
#define PTS   1024
#define KNN   20
#define NPTS  (BATCH*PTS)

// ---------------- device scratch (no allocations allowed) ----------------
__device__ float g_keys[NPTS*1024];   // full pairwise key matrix (134MB), reused
__device__ int   g_idx1[NPTS*KNN];    // kNN in pos space
__device__ float g_x1  [NPTS*64];     // conv1 output
__device__ float g_x1sq[NPTS];        // |x1|^2 per point
__device__ int   g_idx2[NPTS*KNN];    // kNN in feature space
__device__ float g_z   [NPTS*128];    // x1_j @ Wb
__device__ float g_s   [NPTS*128];    // x1_i @ (Wt-Wb) + b
__device__ float g_x2  [NPTS*128];    // conv2 output

// ordered-uint encoding for float atomicMax (handles negatives)
__device__ __forceinline__ unsigned f2key(float f){
    unsigned u = __float_as_uint(f);
    return (u & 0x80000000u) ? ~u : (u | 0x80000000u);
}
__device__ __forceinline__ float key2f(unsigned u){
    unsigned b = (u & 0x80000000u) ? (u & 0x7FFFFFFFu) : ~u;
    return __uint_as_float(b);
}

// ---------------- init + decode output ----------------
__global__ void init_out_kernel(unsigned* out){
    int t = blockIdx.x*blockDim.x + threadIdx.x;
    if (t < BATCH*128) out[t] = 0u;   // encodes -inf
}
__global__ void decode_out_kernel(unsigned* out){
    int t = blockIdx.x*blockDim.x + threadIdx.x;
    if (t < BATCH*128) out[t] = __float_as_uint(key2f(out[t]));
}

// ---------------- kernel A: pairwise 3D distances -> g_keys ----------------
// grid (8 jt, 8 it, 32 clouds), block 256 = 16x16, 8x8 outputs per thread.
__global__ __launch_bounds__(256) void dist_pos_kernel(const float* __restrict__ pos){
    __shared__ float si[3][128], sj[3][128];
    int cloud = blockIdx.z, base = cloud*PTS;
    int i0 = blockIdx.y*128, j0 = blockIdx.x*128;
    int tid = threadIdx.x;
    if (tid < 128){
        const float* p = &pos[(base+i0+tid)*3];
        si[0][tid]=p[0]; si[1][tid]=p[1]; si[2][tid]=p[2];
    } else {
        int t = tid-128;
        const float* p = &pos[(base+j0+t)*3];
        sj[0][t]=p[0]; sj[1][t]=p[1]; sj[2][t]=p[2];
    }
    __syncthreads();
    int tx = tid & 15, ty = tid >> 4;
    float bx[8], by[8], bz[8];
    #pragma unroll
    for (int c=0;c<8;c++){ bx[c]=sj[0][tx*8+c]; by[c]=sj[1][tx*8+c]; bz[c]=sj[2][tx*8+c]; }
    #pragma unroll
    for (int r=0;r<8;r++){
        int row = ty*8+r;
        float ax = si[0][row], ay = si[1][row], az = si[2][row];
        float4 o0, o1;
        float d[8];
        #pragma unroll
        for (int c=0;c<8;c++){
            float dx = ax-bx[c], dy = ay-by[c], dz = az-bz[c];
            d[c] = dx*dx + dy*dy + dz*dz;
        }
        o0 = make_float4(d[0],d[1],d[2],d[3]);
        o1 = make_float4(d[4],d[5],d[6],d[7]);
        float* dst = &g_keys[(base+i0+row)*1024 + j0 + tx*8];
        *(float4*)dst     = o0;
        *(float4*)(dst+4) = o1;
    }
}

// ---------------- kernel B: Gram-based feature keys -> g_keys ----------------
// key[i][j] = |xj|^2 - 2 <xi,xj>  (== dist - |xi|^2, same per-row ordering)
// grid (8 jt, 8 it, 32 clouds), block 512 = 16x32, 4x8 outputs per thread.
__global__ __launch_bounds__(512) void feat_keys_kernel(){
    extern __shared__ float sm[];
    float* sXi = sm;          // 128*64, XOR-swizzled float4 groups
    float* sXj = sm + 8192;
    float* sSq = sm + 16384;  // 128
    int cloud = blockIdx.z, base = cloud*PTS;
    int i0 = blockIdx.y*128, j0 = blockIdx.x*128;
    int tid = threadIdx.x;
    for (int t = tid; t < 2048; t += 512){
        int row = t >> 4, g = t & 15;
        float4 v = *(const float4*)&g_x1[(base+i0+row)*64 + g*4];
        *(float4*)&sXi[row*64 + ((g ^ (row>>3))<<2)] = v;
    }
    for (int t = tid; t < 2048; t += 512){
        int row = t >> 4, g = t & 15;
        float4 v = *(const float4*)&g_x1[(base+j0+row)*64 + g*4];
        *(float4*)&sXj[row*64 + ((g ^ (row>>3))<<2)] = v;
    }
    if (tid < 128) sSq[tid] = g_x1sq[base+j0+tid];
    __syncthreads();

    int tx = tid & 15, ty = tid >> 4;        // ty 0..31: 4 rows; tx: 8 cols
    int aswz = ty >> 1;                      // (ty*4+r)>>3, constant over r
    float acc[4][8];
    #pragma unroll
    for (int r=0;r<4;r++)
        #pragma unroll
        for (int c=0;c<8;c++) acc[r][c] = 0.f;

    #pragma unroll 4
    for (int k4=0;k4<16;k4++){
        float4 a4[4], b4[8];
        int ag = ((k4 ^ aswz) << 2), bg = ((k4 ^ tx) << 2);
        #pragma unroll
        for (int r=0;r<4;r++) a4[r] = *(const float4*)&sXi[(ty*4+r)*64 + ag];
        #pragma unroll
        for (int c=0;c<8;c++) b4[c] = *(const float4*)&sXj[(tx*8+c)*64 + bg];
        #pragma unroll
        for (int r=0;r<4;r++)
            #pragma unroll
            for (int c=0;c<8;c++){
                acc[r][c] += a4[r].x*b4[c].x;
                acc[r][c] += a4[r].y*b4[c].y;
                acc[r][c] += a4[r].z*b4[c].z;
                acc[r][c] += a4[r].w*b4[c].w;
            }
    }

    #pragma unroll
    for (int r=0;r<4;r++){
        int row = ty*4+r;
        float4 o0, o1;
        o0.x = fmaf(-2.f, acc[r][0], sSq[tx*8+0]);
        o0.y = fmaf(-2.f, acc[r][1], sSq[tx*8+1]);
        o0.z = fmaf(-2.f, acc[r][2], sSq[tx*8+2]);
        o0.w = fmaf(-2.f, acc[r][3], sSq[tx*8+3]);
        o1.x = fmaf(-2.f, acc[r][4], sSq[tx*8+4]);
        o1.y = fmaf(-2.f, acc[r][5], sSq[tx*8+5]);
        o1.z = fmaf(-2.f, acc[r][6], sSq[tx*8+6]);
        o1.w = fmaf(-2.f, acc[r][7], sSq[tx*8+7]);
        float* dst = &g_keys[(base+i0+row)*1024 + j0 + tx*8];
        *(float4*)dst     = o0;
        *(float4*)(dst+4) = o1;
    }
}

// ---------------- kernel C: top-20 selection from g_keys rows ----------------
// block 256 = 64 rows x 4 splits; each thread scans 256 keys (coalesced float4),
// register top-20, then smem rank-merge of 4x20 candidates per row.
__global__ __launch_bounds__(256) void select_kernel(int* __restrict__ outIdx){
    __shared__ float mk[64*80];
    int tid = threadIdx.x;
    int rl = tid >> 2, s = tid & 3;
    int row = blockIdx.x*64 + rl;
    int jbase = (row >> 10) << 10;
    const float4* krow = (const float4*)&g_keys[row*1024];

    float bd[KNN]; int bj[KNN];
    #pragma unroll
    for (int k=0;k<KNN;k++){ bd[k]=FLT_MAX; bj[k]=row & 1023; }
    float worst = FLT_MAX; int wpos = 0;

    auto ins = [&](float d, int j){
        if (d < worst){
            bd[wpos]=d; bj[wpos]=j;
            worst = bd[0]; wpos = 0;
            #pragma unroll
            for (int k=1;k<KNN;k++) if (bd[k] > worst){ worst = bd[k]; wpos = k; }
        }
    };

    for (int c = s; c < 256; c += 4){
        float4 v = krow[c];
        int j0 = c*4;
        ins(v.x, j0); ins(v.y, j0+1); ins(v.z, j0+2); ins(v.w, j0+3);
    }

    int cb = rl*80, off = s*20;
    #pragma unroll
    for (int k=0;k<KNN;k++) mk[cb+off+k] = bd[k];
    __syncthreads();
    #pragma unroll
    for (int k=0;k<KNN;k++){
        float kc = bd[k]; int cpos = off + k;
        int rank = 0;
        for (int q=0;q<80;q++){
            float kq = mk[cb+q];
            rank += (kq < kc) || (kq == kc && q < cpos);
        }
        if (rank < KNN) outIdx[row*KNN+rank] = jbase + bj[k];
    }
}

// ---------------- kernel 2: EdgeConv1 (warp per point) — R3 version ----------------
__global__ __launch_bounds__(128) void conv1_kernel(
    const float* __restrict__ pos,
    const float* __restrict__ W1, const float* __restrict__ b1,
    const float* __restrict__ bns, const float* __restrict__ bnb,
    const float* __restrict__ W2, const float* __restrict__ b2)
{
    __shared__ float sW1f[6*64];
    __shared__ float sb1f[64];
    __shared__ float sW2[64*64];
    __shared__ float sb2[64];
    __shared__ float sH[4][KNN*64];

    int tid = threadIdx.x;
    for (int t = tid; t < 64; t += 128){
        float sc = bns[t];
        sb1f[t] = b1[t]*sc + bnb[t];    // fold BN into layer-1 affine
        sb2[t]  = b2[t];
        #pragma unroll
        for (int d=0; d<6; d++) sW1f[d*64+t] = W1[d*64+t]*sc;
    }
    for (int t = tid; t < 4096; t += 128) sW2[t] = W2[t];
    __syncthreads();

    int warp = tid >> 5, lane = tid & 31;
    int i = blockIdx.x*4 + warp;
    float xi0 = pos[i*3+0], xi1 = pos[i*3+1], xi2 = pos[i*3+2];
    float* H = sH[warp];
    int c0 = lane, c1 = lane + 32;

    float w3a = sW1f[192+c0], w4a = sW1f[256+c0], w5a = sW1f[320+c0];
    float w3b = sW1f[192+c1], w4b = sW1f[256+c1], w5b = sW1f[320+c1];
    float basea = sb1f[c0] + xi0*sW1f[c0] + xi1*sW1f[64+c0] + xi2*sW1f[128+c0];
    float baseb = sb1f[c1] + xi0*sW1f[c1] + xi1*sW1f[64+c1] + xi2*sW1f[128+c1];

    #pragma unroll
    for (int j=0;j<KNN;j++){
        int n = g_idx1[i*KNN+j];
        float d0 = pos[n*3+0]-xi0, d1 = pos[n*3+1]-xi1, d2 = pos[n*3+2]-xi2;
        H[j*64+c0] = fmaxf(basea + d0*w3a + d1*w4a + d2*w5a, 0.f);
        H[j*64+c1] = fmaxf(baseb + d0*w3b + d1*w4b + d2*w5b, 0.f);
    }
    __syncwarp();

    float sq = 0.f;
    #pragma unroll
    for (int p=0;p<2;p++){
        int c = lane + 32*p;
        float acc[KNN];
        #pragma unroll
        for (int j=0;j<KNN;j++) acc[j] = 0.f;
        for (int k4=0;k4<64;k4+=4){
            float q0 = sW2[(k4+0)*64+c];
            float q1 = sW2[(k4+1)*64+c];
            float q2 = sW2[(k4+2)*64+c];
            float q3 = sW2[(k4+3)*64+c];
            #pragma unroll
            for (int j=0;j<KNN;j++){
                float4 h = *(const float4*)&H[j*64+k4];
                acc[j] += h.x*q0 + h.y*q1 + h.z*q2 + h.w*q3;
            }
        }
        float m = acc[0];
        #pragma unroll
        for (int j=1;j<KNN;j++) m = fmaxf(m, acc[j]);
        m += sb2[c];
        g_x1[i*64+c] = m;
        sq += m*m;
    }
    #pragma unroll
    for (int o=16;o;o>>=1) sq += __shfl_xor_sync(0xffffffffu, sq, o);
    if (lane == 0) g_x1sq[i] = sq;
}

// ---------------- kernel 4: z = x1@Wb, s = x1@(Wt-Wb)+b ----------------
__global__ __launch_bounds__(256) void zs_kernel(const float* __restrict__ c2W,
                                                 const float* __restrict__ c2b){
    extern __shared__ float sm4[];
    float* sW = sm4;            // 128*128
    float* sx = sm4 + 16384;    // 8 warps * 2 pts * 64
    int tid = threadIdx.x, warp = tid>>5, lane = tid&31;
    for (int t=tid; t<16384; t+=256) sW[t] = c2W[t];
    __syncthreads();
    float cbv[4];
    #pragma unroll
    for (int q=0;q<4;q++) cbv[q] = c2b[lane+32*q];

    for (int g = blockIdx.x; g < NPTS/16; g += gridDim.x){
        int i0 = g*16 + warp*2;
        float* xw = sx + warp*128;
        xw[lane]      = g_x1[i0*64 + lane];
        xw[lane+32]   = g_x1[i0*64 + 32 + lane];
        xw[64+lane]   = g_x1[(i0+1)*64 + lane];
        xw[96+lane]   = g_x1[(i0+1)*64 + 32 + lane];
        __syncwarp();
        float az0[4]={0,0,0,0}, az1[4]={0,0,0,0}, at0[4]={0,0,0,0}, at1[4]={0,0,0,0};
        for (int k=0;k<64;k++){
            float x0 = xw[k], x1v = xw[64+k];
            #pragma unroll
            for (int q=0;q<4;q++){
                int c = lane + 32*q;
                float wt = sW[k*128+c];
                float wb = sW[(k+64)*128+c];
                at0[q] += x0*wt;  az0[q] += x0*wb;
                at1[q] += x1v*wt; az1[q] += x1v*wb;
            }
        }
        #pragma unroll
        for (int q=0;q<4;q++){
            int c = lane + 32*q;
            g_z[i0*128+c]     = az0[q];
            g_s[i0*128+c]     = at0[q]-az0[q]+cbv[q];
            g_z[(i0+1)*128+c] = az1[q];
            g_s[(i0+1)*128+c] = at1[q]-az1[q]+cbv[q];
        }
        __syncwarp();
    }
}

// ---------------- kernel 5: gather-max -> x2 ----------------
__global__ __launch_bounds__(256) void gather_kernel(){
    int gw   = (blockIdx.x*blockDim.x + threadIdx.x) >> 5;
    int lane = threadIdx.x & 31;
    if (gw >= NPTS) return;
    const int* idx = &g_idx2[gw*KNN];
    float4 m = make_float4(-FLT_MAX,-FLT_MAX,-FLT_MAX,-FLT_MAX);
    #pragma unroll
    for (int j=0;j<KNN;j++){
        int n = idx[j];
        float4 v = *(const float4*)&g_z[n*128 + lane*4];
        m.x = fmaxf(m.x, v.x); m.y = fmaxf(m.y, v.y);
        m.z = fmaxf(m.z, v.z); m.w = fmaxf(m.w, v.w);
    }
    float4 sv = *(const float4*)&g_s[gw*128 + lane*4];
    float4 r  = make_float4(sv.x+m.x, sv.y+m.y, sv.z+m.z, sv.w+m.w);
    *(float4*)&g_x2[gw*128 + lane*4] = r;
}

// ---------------- kernel 6: lin([x1,x2]) + global max pool ----------------
__global__ __launch_bounds__(512) void linpool_kernel(const float* __restrict__ lW,
                                                      const float* __restrict__ lb,
                                                      unsigned* __restrict__ out){
    extern __shared__ float sm6[];
    float* sW = sm6;              // 192*128
    float* sx = sm6 + 192*128;    // 16 warps * 4 pts * 192
    int tid = threadIdx.x, warp = tid>>5, lane = tid&31;
    for (int t=tid; t<192*128; t+=512) sW[t] = lW[t];
    __syncthreads();
    float lbv[4];
    #pragma unroll
    for (int q=0;q<4;q++) lbv[q] = lb[lane+32*q];

    for (int ch = blockIdx.x*16 + warp; ch < NPTS/4; ch += gridDim.x*16){
        int p0 = ch*4;
        float* xw = sx + warp*4*192;
        #pragma unroll
        for (int pt=0; pt<4; pt++){
            int p = p0 + pt;
            #pragma unroll
            for (int t6=0; t6<6; t6++){
                int t = lane + t6*32;
                xw[pt*192 + t] = (t < 64) ? g_x1[p*64 + t] : g_x2[p*128 + (t-64)];
            }
        }
        __syncwarp();
        float acc[4][4];
        #pragma unroll
        for (int pt=0;pt<4;pt++)
            #pragma unroll
            for (int q=0;q<4;q++) acc[pt][q] = 0.f;
        #pragma unroll 4
        for (int k=0;k<192;k++){
            float w0 = sW[k*128+lane],    w1 = sW[k*128+lane+32];
            float w2 = sW[k*128+lane+64], w3 = sW[k*128+lane+96];
            #pragma unroll
            for (int pt=0;pt<4;pt++){
                float xv = xw[pt*192+k];
                acc[pt][0] += xv*w0; acc[pt][1] += xv*w1;
                acc[pt][2] += xv*w2; acc[pt][3] += xv*w3;
            }
        }
        int cloud = p0 >> 10;
        #pragma unroll
        for (int q=0;q<4;q++){
            float m = fmaxf(fmaxf(acc[0][q],acc[1][q]), fmaxf(acc[2][q],acc[3][q])) + lbv[q];
            atomicMax(&out[cloud*128 + lane + 32*q], f2key(m));
        }
        __syncwarp();
    }
}

// ---------------- launch ----------------
extern "C" void kernel_launch(void* const* d_in, const int* in_sizes, int n_in,
                              void* d_out, int out_size)
{
    const float* pos  = (const float*)d_in[0];
    const float* c1W1 = (const float*)d_in[2];
    const float* c1b1 = (const float*)d_in[3];
    const float* bns  = (const float*)d_in[4];
    const float* bnb  = (const float*)d_in[5];
    const float* c1W2 = (const float*)d_in[6];
    const float* c1b2 = (const float*)d_in[7];
    const float* c2W  = (const float*)d_in[8];
    const float* c2b  = (const float*)d_in[9];
    const float* lW   = (const float*)d_in[10];
    const float* lb   = (const float*)d_in[11];
    unsigned* out = (unsigned*)d_out;

    int* d_idx1; cudaGetSymbolAddress((void**)&d_idx1, g_idx1);
    int* d_idx2; cudaGetSymbolAddress((void**)&d_idx2, g_idx2);

    const int FK_SMEM = (8192*2 + 128) * 4;                // 66,048 B
    const int ZS_SMEM = (16384 + 8*128) * 4;               // 69,632 B
    const int LP_SMEM = (192*128 + 16*4*192) * 4;          // 147,456 B
    cudaFuncSetAttribute(feat_keys_kernel, cudaFuncAttributeMaxDynamicSharedMemorySize, FK_SMEM);
    cudaFuncSetAttribute(zs_kernel,        cudaFuncAttributeMaxDynamicSharedMemorySize, ZS_SMEM);
    cudaFuncSetAttribute(linpool_kernel,   cudaFuncAttributeMaxDynamicSharedMemorySize, LP_SMEM);

    init_out_kernel<<<16, 256>>>(out);
    dist_pos_kernel<<<dim3(8,8,BATCH), 256>>>(pos);
    select_kernel<<<NPTS/64, 256>>>(d_idx1);
    conv1_kernel<<<NPTS/4, 128>>>(pos, c1W1, c1b1, bns, bnb, c1W2, c1b2);
    feat_keys_kernel<<<dim3(8,8,BATCH), 512, FK_SMEM>>>();
    select_kernel<<<NPTS/64, 256>>>(d_idx2);
    zs_kernel<<<444, 256, ZS_SMEM>>>(c2W, c2b);
    gather_kernel<<<NPTS/8, 256>>>();
    linpool_kernel<<<148, 512, LP_SMEM>>>(lW, lb, out);
    decode_out_kernel<<<16, 256>>>(out);
}

// round 7
// speedup vs baseline: 1.5288x; 1.0446x over previous
#include <cuda_runtime.h>
#include <cfloat>
#include <cstdint>

#define BATCH 32
#define PTS   1024
#define KNN   20
#define NPTS  (BATCH*PTS)

// ---------------- device scratch (no allocations allowed) ----------------
__device__ float g_keys[NPTS*1024];   // full pairwise key matrix (134MB), reused
__device__ int   g_idx1[NPTS*KNN];    // kNN in pos space
__device__ float g_x1  [NPTS*64];     // conv1 output
__device__ float g_x1sq[NPTS];        // |x1|^2 per point
__device__ int   g_idx2[NPTS*KNN];    // kNN in feature space
__device__ float g_z   [NPTS*128];    // x1_j @ Wb
__device__ float g_s   [NPTS*128];    // x1_i @ (Wt-Wb) + b
__device__ float g_x2  [NPTS*128];    // conv2 output

// ordered-uint encoding for float atomicMax (handles negatives)
__device__ __forceinline__ unsigned f2key(float f){
    unsigned u = __float_as_uint(f);
    return (u & 0x80000000u) ? ~u : (u | 0x80000000u);
}
__device__ __forceinline__ float key2f(unsigned u){
    unsigned b = (u & 0x80000000u) ? (u & 0x7FFFFFFFu) : ~u;
    return __uint_as_float(b);
}

// ---------------- init + decode output ----------------
__global__ void init_out_kernel(unsigned* out){
    int t = blockIdx.x*blockDim.x + threadIdx.x;
    if (t < BATCH*128) out[t] = 0u;   // encodes -inf
}
__global__ void decode_out_kernel(unsigned* out){
    int t = blockIdx.x*blockDim.x + threadIdx.x;
    if (t < BATCH*128) out[t] = __float_as_uint(key2f(out[t]));
}

// ---------------- kernel A: pairwise 3D distances -> g_keys ----------------
__global__ __launch_bounds__(256) void dist_pos_kernel(const float* __restrict__ pos){
    __shared__ float si[3][128], sj[3][128];
    int cloud = blockIdx.z, base = cloud*PTS;
    int i0 = blockIdx.y*128, j0 = blockIdx.x*128;
    int tid = threadIdx.x;
    if (tid < 128){
        const float* p = &pos[(base+i0+tid)*3];
        si[0][tid]=p[0]; si[1][tid]=p[1]; si[2][tid]=p[2];
    } else {
        int t = tid-128;
        const float* p = &pos[(base+j0+t)*3];
        sj[0][t]=p[0]; sj[1][t]=p[1]; sj[2][t]=p[2];
    }
    __syncthreads();
    int tx = tid & 15, ty = tid >> 4;
    float bx[8], by[8], bz[8];
    #pragma unroll
    for (int c=0;c<8;c++){ bx[c]=sj[0][tx*8+c]; by[c]=sj[1][tx*8+c]; bz[c]=sj[2][tx*8+c]; }
    #pragma unroll
    for (int r=0;r<8;r++){
        int row = ty*8+r;
        float ax = si[0][row], ay = si[1][row], az = si[2][row];
        float d[8];
        #pragma unroll
        for (int c=0;c<8;c++){
            float dx = ax-bx[c], dy = ay-by[c], dz = az-bz[c];
            d[c] = dx*dx + dy*dy + dz*dz;
        }
        float* dst = &g_keys[(base+i0+row)*1024 + j0 + tx*8];
        *(float4*)dst     = make_float4(d[0],d[1],d[2],d[3]);
        *(float4*)(dst+4) = make_float4(d[4],d[5],d[6],d[7]);
    }
}

// ---------------- kernel B: Gram-based feature keys -> g_keys ----------------
__global__ __launch_bounds__(512) void feat_keys_kernel(){
    extern __shared__ float sm[];
    float* sXi = sm;          // 128*64, XOR-swizzled float4 groups
    float* sXj = sm + 8192;
    float* sSq = sm + 16384;  // 128
    int cloud = blockIdx.z, base = cloud*PTS;
    int i0 = blockIdx.y*128, j0 = blockIdx.x*128;
    int tid = threadIdx.x;
    for (int t = tid; t < 2048; t += 512){
        int row = t >> 4, g = t & 15;
        float4 v = *(const float4*)&g_x1[(base+i0+row)*64 + g*4];
        *(float4*)&sXi[row*64 + ((g ^ (row>>3))<<2)] = v;
    }
    for (int t = tid; t < 2048; t += 512){
        int row = t >> 4, g = t & 15;
        float4 v = *(const float4*)&g_x1[(base+j0+row)*64 + g*4];
        *(float4*)&sXj[row*64 + ((g ^ (row>>3))<<2)] = v;
    }
    if (tid < 128) sSq[tid] = g_x1sq[base+j0+tid];
    __syncthreads();

    int tx = tid & 15, ty = tid >> 4;        // ty 0..31: 4 rows; tx: 8 cols
    int aswz = ty >> 1;                      // (ty*4+r)>>3, constant over r
    float acc[4][8];
    #pragma unroll
    for (int r=0;r<4;r++)
        #pragma unroll
        for (int c=0;c<8;c++) acc[r][c] = 0.f;

    #pragma unroll 4
    for (int k4=0;k4<16;k4++){
        float4 a4[4], b4[8];
        int ag = ((k4 ^ aswz) << 2), bg = ((k4 ^ tx) << 2);
        #pragma unroll
        for (int r=0;r<4;r++) a4[r] = *(const float4*)&sXi[(ty*4+r)*64 + ag];
        #pragma unroll
        for (int c=0;c<8;c++) b4[c] = *(const float4*)&sXj[(tx*8+c)*64 + bg];
        #pragma unroll
        for (int r=0;r<4;r++)
            #pragma unroll
            for (int c=0;c<8;c++){
                acc[r][c] += a4[r].x*b4[c].x;
                acc[r][c] += a4[r].y*b4[c].y;
                acc[r][c] += a4[r].z*b4[c].z;
                acc[r][c] += a4[r].w*b4[c].w;
            }
    }

    #pragma unroll
    for (int r=0;r<4;r++){
        int row = ty*4+r;
        float4 o0, o1;
        o0.x = fmaf(-2.f, acc[r][0], sSq[tx*8+0]);
        o0.y = fmaf(-2.f, acc[r][1], sSq[tx*8+1]);
        o0.z = fmaf(-2.f, acc[r][2], sSq[tx*8+2]);
        o0.w = fmaf(-2.f, acc[r][3], sSq[tx*8+3]);
        o1.x = fmaf(-2.f, acc[r][4], sSq[tx*8+4]);
        o1.y = fmaf(-2.f, acc[r][5], sSq[tx*8+5]);
        o1.z = fmaf(-2.f, acc[r][6], sSq[tx*8+6]);
        o1.w = fmaf(-2.f, acc[r][7], sSq[tx*8+7]);
        float* dst = &g_keys[(base+i0+row)*1024 + j0 + tx*8];
        *(float4*)dst     = o0;
        *(float4*)(dst+4) = o1;
    }
}

// ---------------- kernel C: top-20 selection from g_keys rows ----------------
__global__ __launch_bounds__(256) void select_kernel(int* __restrict__ outIdx){
    __shared__ float mk[64*80];
    int tid = threadIdx.x;
    int rl = tid >> 2, s = tid & 3;
    int row = blockIdx.x*64 + rl;
    int jbase = (row >> 10) << 10;
    const float4* krow = (const float4*)&g_keys[row*1024];

    float bd[KNN]; int bj[KNN];
    #pragma unroll
    for (int k=0;k<KNN;k++){ bd[k]=FLT_MAX; bj[k]=row & 1023; }
    float worst = FLT_MAX; int wpos = 0;

    auto ins = [&](float d, int j){
        if (d < worst){
            bd[wpos]=d; bj[wpos]=j;
            worst = bd[0]; wpos = 0;
            #pragma unroll
            for (int k=1;k<KNN;k++) if (bd[k] > worst){ worst = bd[k]; wpos = k; }
        }
    };

    for (int c = s; c < 256; c += 4){
        float4 v = krow[c];
        int j0 = c*4;
        ins(v.x, j0); ins(v.y, j0+1); ins(v.z, j0+2); ins(v.w, j0+3);
    }

    int cb = rl*80, off = s*20;
    #pragma unroll
    for (int k=0;k<KNN;k++) mk[cb+off+k] = bd[k];
    __syncthreads();
    #pragma unroll
    for (int k=0;k<KNN;k++){
        float kc = bd[k]; int cpos = off + k;
        int rank = 0;
        for (int q=0;q<80;q++){
            float kq = mk[cb+q];
            rank += (kq < kc) || (kq == kc && q < cpos);
        }
        if (rank < KNN) outIdx[row*KNN+rank] = jbase + bj[k];
    }
}

// ---------------- kernel 2: EdgeConv1 — 8 warps/block, fused dual-column layer2 ----
// dyn smem layout (floats): sW1f[384] | sb1f[64] | sb2[64] | sW2[4096] | sH[8][1280]
__global__ __launch_bounds__(256) void conv1_kernel(
    const float* __restrict__ pos,
    const float* __restrict__ W1, const float* __restrict__ b1,
    const float* __restrict__ bns, const float* __restrict__ bnb,
    const float* __restrict__ W2, const float* __restrict__ b2)
{
    extern __shared__ float smc[];
    float* sW1f = smc;            // 384
    float* sb1f = smc + 384;      // 64
    float* sb2  = smc + 448;      // 64
    float* sW2  = smc + 512;      // 4096
    float* sHb  = smc + 4608;     // 8*1280

    int tid = threadIdx.x;
    for (int t = tid; t < 64; t += 256){
        float sc = bns[t];
        sb1f[t] = b1[t]*sc + bnb[t];    // fold BN into layer-1 affine
        sb2[t]  = b2[t];
        #pragma unroll
        for (int d=0; d<6; d++) sW1f[d*64+t] = W1[d*64+t]*sc;
    }
    for (int t = tid; t < 4096; t += 256) sW2[t] = W2[t];
    __syncthreads();

    int warp = tid >> 5, lane = tid & 31;
    int i = blockIdx.x*8 + warp;
    float xi0 = pos[i*3+0], xi1 = pos[i*3+1], xi2 = pos[i*3+2];
    float* H = sHb + warp*1280;
    int c0 = lane, c1 = lane + 32;

    float w3a = sW1f[192+c0], w4a = sW1f[256+c0], w5a = sW1f[320+c0];
    float w3b = sW1f[192+c1], w4b = sW1f[256+c1], w5b = sW1f[320+c1];
    float basea = sb1f[c0] + xi0*sW1f[c0] + xi1*sW1f[64+c0] + xi2*sW1f[128+c0];
    float baseb = sb1f[c1] + xi0*sW1f[c1] + xi1*sW1f[64+c1] + xi2*sW1f[128+c1];

    // layer 1: per-edge hidden, relu, to shared
    #pragma unroll
    for (int j=0;j<KNN;j++){
        int n = g_idx1[i*KNN+j];
        float d0 = pos[n*3+0]-xi0, d1 = pos[n*3+1]-xi1, d2 = pos[n*3+2]-xi2;
        H[j*64+c0] = fmaxf(basea + d0*w3a + d1*w4a + d2*w5a, 0.f);
        H[j*64+c1] = fmaxf(baseb + d0*w3b + d1*w4b + d2*w5b, 0.f);
    }
    __syncwarp();

    // layer 2: both column sets in ONE k-sweep (each H read feeds 8 FMAs)
    float acc0[KNN], acc1[KNN];
    #pragma unroll
    for (int j=0;j<KNN;j++){ acc0[j]=0.f; acc1[j]=0.f; }
    for (int k4=0;k4<64;k4+=4){
        float p0 = sW2[(k4+0)*64+c0], q0 = sW2[(k4+0)*64+c1];
        float p1 = sW2[(k4+1)*64+c0], q1 = sW2[(k4+1)*64+c1];
        float p2 = sW2[(k4+2)*64+c0], q2 = sW2[(k4+2)*64+c1];
        float p3 = sW2[(k4+3)*64+c0], q3 = sW2[(k4+3)*64+c1];
        #pragma unroll
        for (int j=0;j<KNN;j++){
            float4 h = *(const float4*)&H[j*64+k4];
            acc0[j] += h.x*p0 + h.y*p1 + h.z*p2 + h.w*p3;
            acc1[j] += h.x*q0 + h.y*q1 + h.z*q2 + h.w*q3;
        }
    }
    float m0 = acc0[0], m1 = acc1[0];
    #pragma unroll
    for (int j=1;j<KNN;j++){ m0 = fmaxf(m0, acc0[j]); m1 = fmaxf(m1, acc1[j]); }
    m0 += sb2[c0];
    m1 += sb2[c1];
    g_x1[i*64+c0] = m0;
    g_x1[i*64+c1] = m1;
    float sq = m0*m0 + m1*m1;
    #pragma unroll
    for (int o=16;o;o>>=1) sq += __shfl_xor_sync(0xffffffffu, sq, o);
    if (lane == 0) g_x1sq[i] = sq;
}

// ---------------- kernel 4: z = x1@Wb, s = x1@(Wt-Wb)+b ----------------
__global__ __launch_bounds__(256) void zs_kernel(const float* __restrict__ c2W,
                                                 const float* __restrict__ c2b){
    extern __shared__ float sm4[];
    float* sW = sm4;            // 128*128
    float* sx = sm4 + 16384;    // 8 warps * 2 pts * 64
    int tid = threadIdx.x, warp = tid>>5, lane = tid&31;
    for (int t=tid; t<16384; t+=256) sW[t] = c2W[t];
    __syncthreads();
    float cbv[4];
    #pragma unroll
    for (int q=0;q<4;q++) cbv[q] = c2b[lane+32*q];

    for (int g = blockIdx.x; g < NPTS/16; g += gridDim.x){
        int i0 = g*16 + warp*2;
        float* xw = sx + warp*128;
        xw[lane]      = g_x1[i0*64 + lane];
        xw[lane+32]   = g_x1[i0*64 + 32 + lane];
        xw[64+lane]   = g_x1[(i0+1)*64 + lane];
        xw[96+lane]   = g_x1[(i0+1)*64 + 32 + lane];
        __syncwarp();
        float az0[4]={0,0,0,0}, az1[4]={0,0,0,0}, at0[4]={0,0,0,0}, at1[4]={0,0,0,0};
        for (int k=0;k<64;k++){
            float x0 = xw[k], x1v = xw[64+k];
            #pragma unroll
            for (int q=0;q<4;q++){
                int c = lane + 32*q;
                float wt = sW[k*128+c];
                float wb = sW[(k+64)*128+c];
                at0[q] += x0*wt;  az0[q] += x0*wb;
                at1[q] += x1v*wt; az1[q] += x1v*wb;
            }
        }
        #pragma unroll
        for (int q=0;q<4;q++){
            int c = lane + 32*q;
            g_z[i0*128+c]     = az0[q];
            g_s[i0*128+c]     = at0[q]-az0[q]+cbv[q];
            g_z[(i0+1)*128+c] = az1[q];
            g_s[(i0+1)*128+c] = at1[q]-az1[q]+cbv[q];
        }
        __syncwarp();
    }
}

// ---------------- kernel 5: gather-max -> x2 ----------------
__global__ __launch_bounds__(256) void gather_kernel(){
    int gw   = (blockIdx.x*blockDim.x + threadIdx.x) >> 5;
    int lane = threadIdx.x & 31;
    if (gw >= NPTS) return;
    const int* idx = &g_idx2[gw*KNN];
    float4 m = make_float4(-FLT_MAX,-FLT_MAX,-FLT_MAX,-FLT_MAX);
    #pragma unroll
    for (int j=0;j<KNN;j++){
        int n = idx[j];
        float4 v = *(const float4*)&g_z[n*128 + lane*4];
        m.x = fmaxf(m.x, v.x); m.y = fmaxf(m.y, v.y);
        m.z = fmaxf(m.z, v.z); m.w = fmaxf(m.w, v.w);
    }
    float4 sv = *(const float4*)&g_s[gw*128 + lane*4];
    float4 r  = make_float4(sv.x+m.x, sv.y+m.y, sv.z+m.z, sv.w+m.w);
    *(float4*)&g_x2[gw*128 + lane*4] = r;
}

// ---------------- kernel 6: lin([x1,x2]) + global max pool ----------------
__global__ __launch_bounds__(512) void linpool_kernel(const float* __restrict__ lW,
                                                      const float* __restrict__ lb,
                                                      unsigned* __restrict__ out){
    extern __shared__ float sm6[];
    float* sW = sm6;              // 192*128
    float* sx = sm6 + 192*128;    // 16 warps * 4 pts * 192
    int tid = threadIdx.x, warp = tid>>5, lane = tid&31;
    for (int t=tid; t<192*128; t+=512) sW[t] = lW[t];
    __syncthreads();
    float lbv[4];
    #pragma unroll
    for (int q=0;q<4;q++) lbv[q] = lb[lane+32*q];

    for (int ch = blockIdx.x*16 + warp; ch < NPTS/4; ch += gridDim.x*16){
        int p0 = ch*4;
        float* xw = sx + warp*4*192;
        #pragma unroll
        for (int pt=0; pt<4; pt++){
            int p = p0 + pt;
            #pragma unroll
            for (int t6=0; t6<6; t6++){
                int t = lane + t6*32;
                xw[pt*192 + t] = (t < 64) ? g_x1[p*64 + t] : g_x2[p*128 + (t-64)];
            }
        }
        __syncwarp();
        float acc[4][4];
        #pragma unroll
        for (int pt=0;pt<4;pt++)
            #pragma unroll
            for (int q=0;q<4;q++) acc[pt][q] = 0.f;
        #pragma unroll 4
        for (int k=0;k<192;k++){
            float w0 = sW[k*128+lane],    w1 = sW[k*128+lane+32];
            float w2 = sW[k*128+lane+64], w3 = sW[k*128+lane+96];
            #pragma unroll
            for (int pt=0;pt<4;pt++){
                float xv = xw[pt*192+k];
                acc[pt][0] += xv*w0; acc[pt][1] += xv*w1;
                acc[pt][2] += xv*w2; acc[pt][3] += xv*w3;
            }
        }
        int cloud = p0 >> 10;
        #pragma unroll
        for (int q=0;q<4;q++){
            float m = fmaxf(fmaxf(acc[0][q],acc[1][q]), fmaxf(acc[2][q],acc[3][q])) + lbv[q];
            atomicMax(&out[cloud*128 + lane + 32*q], f2key(m));
        }
        __syncwarp();
    }
}

// ---------------- launch ----------------
extern "C" void kernel_launch(void* const* d_in, const int* in_sizes, int n_in,
                              void* d_out, int out_size)
{
    const float* pos  = (const float*)d_in[0];
    const float* c1W1 = (const float*)d_in[2];
    const float* c1b1 = (const float*)d_in[3];
    const float* bns  = (const float*)d_in[4];
    const float* bnb  = (const float*)d_in[5];
    const float* c1W2 = (const float*)d_in[6];
    const float* c1b2 = (const float*)d_in[7];
    const float* c2W  = (const float*)d_in[8];
    const float* c2b  = (const float*)d_in[9];
    const float* lW   = (const float*)d_in[10];
    const float* lb   = (const float*)d_in[11];
    unsigned* out = (unsigned*)d_out;

    int* d_idx1; cudaGetSymbolAddress((void**)&d_idx1, g_idx1);
    int* d_idx2; cudaGetSymbolAddress((void**)&d_idx2, g_idx2);

    const int C1_SMEM = (4608 + 8*1280) * 4;               // 59,392 B
    const int FK_SMEM = (8192*2 + 128) * 4;                // 66,048 B
    const int ZS_SMEM = (16384 + 8*128) * 4;               // 69,632 B
    const int LP_SMEM = (192*128 + 16*4*192) * 4;          // 147,456 B
    cudaFuncSetAttribute(conv1_kernel,     cudaFuncAttributeMaxDynamicSharedMemorySize, C1_SMEM);
    cudaFuncSetAttribute(feat_keys_kernel, cudaFuncAttributeMaxDynamicSharedMemorySize, FK_SMEM);
    cudaFuncSetAttribute(zs_kernel,        cudaFuncAttributeMaxDynamicSharedMemorySize, ZS_SMEM);
    cudaFuncSetAttribute(linpool_kernel,   cudaFuncAttributeMaxDynamicSharedMemorySize, LP_SMEM);

    init_out_kernel<<<16, 256>>>(out);
    dist_pos_kernel<<<dim3(8,8,BATCH), 256>>>(pos);
    select_kernel<<<NPTS/64, 256>>>(d_idx1);
    conv1_kernel<<<NPTS/8, 256, C1_SMEM>>>(pos, c1W1, c1b1, bns, bnb, c1W2, c1b2);
    feat_keys_kernel<<<dim3(8,8,BATCH), 512, FK_SMEM>>>();
    select_kernel<<<NPTS/64, 256>>>(d_idx2);
    zs_kernel<<<444, 256, ZS_SMEM>>>(c2W, c2b);
    gather_kernel<<<NPTS/8, 256>>>();
    linpool_kernel<<<148, 512, LP_SMEM>>>(lW, lb, out);
    decode_out_kernel<<<16, 256>>>(out);
}

// round 10
// speedup vs baseline: 1.5985x; 1.0456x over previous
#include <cuda_runtime.h>
#include <cfloat>
#include <cstdint>

#define BATCH 32
#define PTS   1024
#define KNN   20
#define NPTS  (BATCH*PTS)

// ---------------- device scratch (no allocations allowed) ----------------
__device__ float g_keys[NPTS*1024];   // full pairwise key matrix (134MB), reused
__device__ int   g_idx1[NPTS*KNN];    // kNN in pos space
__device__ float g_x1  [NPTS*64];     // conv1 output
__device__ float g_x1sq[NPTS];        // |x1|^2 per point
__device__ int   g_idx2[NPTS*KNN];    // kNN in feature space
__device__ float g_z   [NPTS*128];    // x1_j @ Wb
__device__ float g_s   [NPTS*128];    // x1_i @ (Wt-Wb) + b
__device__ float g_x2  [NPTS*128];    // conv2 output

// packed fp32x2 fma (Blackwell FFMA2): d = a*b + c lane-wise, exact fp32 FMA
__device__ __forceinline__ float2 ffma2(float2 a, float2 b, float2 c){
    float2 d;
    asm("fma.rn.f32x2 %0, %1, %2, %3;"
        : "=l"(*(unsigned long long*)&d)
        : "l"(*(unsigned long long*)&a),
          "l"(*(unsigned long long*)&b),
          "l"(*(unsigned long long*)&c));
    return d;
}

// ordered-uint encoding for float atomicMax (handles negatives)
__device__ __forceinline__ unsigned f2key(float f){
    unsigned u = __float_as_uint(f);
    return (u & 0x80000000u) ? ~u : (u | 0x80000000u);
}
__device__ __forceinline__ float key2f(unsigned u){
    unsigned b = (u & 0x80000000u) ? (u & 0x7FFFFFFFu) : ~u;
    return __uint_as_float(b);
}

// ---------------- init + decode output ----------------
__global__ void init_out_kernel(unsigned* out){
    int t = blockIdx.x*blockDim.x + threadIdx.x;
    if (t < BATCH*128) out[t] = 0u;   // encodes -inf
}
__global__ void decode_out_kernel(unsigned* out){
    int t = blockIdx.x*blockDim.x + threadIdx.x;
    if (t < BATCH*128) out[t] = __float_as_uint(key2f(out[t]));
}

// ---------------- kernel A: pairwise 3D distances -> g_keys ----------------
__global__ __launch_bounds__(256) void dist_pos_kernel(const float* __restrict__ pos){
    __shared__ float si[3][128], sj[3][128];
    int cloud = blockIdx.z, base = cloud*PTS;
    int i0 = blockIdx.y*128, j0 = blockIdx.x*128;
    int tid = threadIdx.x;
    if (tid < 128){
        const float* p = &pos[(base+i0+tid)*3];
        si[0][tid]=p[0]; si[1][tid]=p[1]; si[2][tid]=p[2];
    } else {
        int t = tid-128;
        const float* p = &pos[(base+j0+t)*3];
        sj[0][t]=p[0]; sj[1][t]=p[1]; sj[2][t]=p[2];
    }
    __syncthreads();
    int tx = tid & 15, ty = tid >> 4;
    float bx[8], by[8], bz[8];
    #pragma unroll
    for (int c=0;c<8;c++){ bx[c]=sj[0][tx*8+c]; by[c]=sj[1][tx*8+c]; bz[c]=sj[2][tx*8+c]; }
    #pragma unroll
    for (int r=0;r<8;r++){
        int row = ty*8+r;
        float ax = si[0][row], ay = si[1][row], az = si[2][row];
        float d[8];
        #pragma unroll
        for (int c=0;c<8;c++){
            float dx = ax-bx[c], dy = ay-by[c], dz = az-bz[c];
            d[c] = dx*dx + dy*dy + dz*dz;
        }
        float* dst = &g_keys[(base+i0+row)*1024 + j0 + tx*8];
        *(float4*)dst     = make_float4(d[0],d[1],d[2],d[3]);
        *(float4*)(dst+4) = make_float4(d[4],d[5],d[6],d[7]);
    }
}

// ---------------- kernel B: Gram-based feature keys -> g_keys ----------------
__global__ __launch_bounds__(512) void feat_keys_kernel(){
    extern __shared__ float sm[];
    float* sXi = sm;          // 128*64, XOR-swizzled float4 groups
    float* sXj = sm + 8192;
    float* sSq = sm + 16384;  // 128
    int cloud = blockIdx.z, base = cloud*PTS;
    int i0 = blockIdx.y*128, j0 = blockIdx.x*128;
    int tid = threadIdx.x;
    for (int t = tid; t < 2048; t += 512){
        int row = t >> 4, g = t & 15;
        float4 v = *(const float4*)&g_x1[(base+i0+row)*64 + g*4];
        *(float4*)&sXi[row*64 + ((g ^ (row>>3))<<2)] = v;
    }
    for (int t = tid; t < 2048; t += 512){
        int row = t >> 4, g = t & 15;
        float4 v = *(const float4*)&g_x1[(base+j0+row)*64 + g*4];
        *(float4*)&sXj[row*64 + ((g ^ (row>>3))<<2)] = v;
    }
    if (tid < 128) sSq[tid] = g_x1sq[base+j0+tid];
    __syncthreads();

    int tx = tid & 15, ty = tid >> 4;        // ty 0..31: 4 rows; tx: 8 cols
    int aswz = ty >> 1;                      // (ty*4+r)>>3, constant over r
    float acc[4][8];
    #pragma unroll
    for (int r=0;r<4;r++)
        #pragma unroll
        for (int c=0;c<8;c++) acc[r][c] = 0.f;

    #pragma unroll 4
    for (int k4=0;k4<16;k4++){
        float4 a4[4], b4[8];
        int ag = ((k4 ^ aswz) << 2), bg = ((k4 ^ tx) << 2);
        #pragma unroll
        for (int r=0;r<4;r++) a4[r] = *(const float4*)&sXi[(ty*4+r)*64 + ag];
        #pragma unroll
        for (int c=0;c<8;c++) b4[c] = *(const float4*)&sXj[(tx*8+c)*64 + bg];
        #pragma unroll
        for (int r=0;r<4;r++)
            #pragma unroll
            for (int c=0;c<8;c++){
                acc[r][c] += a4[r].x*b4[c].x;
                acc[r][c] += a4[r].y*b4[c].y;
                acc[r][c] += a4[r].z*b4[c].z;
                acc[r][c] += a4[r].w*b4[c].w;
            }
    }

    #pragma unroll
    for (int r=0;r<4;r++){
        int row = ty*4+r;
        float4 o0, o1;
        o0.x = fmaf(-2.f, acc[r][0], sSq[tx*8+0]);
        o0.y = fmaf(-2.f, acc[r][1], sSq[tx*8+1]);
        o0.z = fmaf(-2.f, acc[r][2], sSq[tx*8+2]);
        o0.w = fmaf(-2.f, acc[r][3], sSq[tx*8+3]);
        o1.x = fmaf(-2.f, acc[r][4], sSq[tx*8+4]);
        o1.y = fmaf(-2.f, acc[r][5], sSq[tx*8+5]);
        o1.z = fmaf(-2.f, acc[r][6], sSq[tx*8+6]);
        o1.w = fmaf(-2.f, acc[r][7], sSq[tx*8+7]);
        float* dst = &g_keys[(base+i0+row)*1024 + j0 + tx*8];
        *(float4*)dst     = o0;
        *(float4*)(dst+4) = o1;
    }
}

// ---------------- kernel C: top-20 selection from g_keys rows ----------------
__global__ __launch_bounds__(256) void select_kernel(int* __restrict__ outIdx){
    __shared__ float mk[64*80];
    int tid = threadIdx.x;
    int rl = tid >> 2, s = tid & 3;
    int row = blockIdx.x*64 + rl;
    int jbase = (row >> 10) << 10;
    const float4* krow = (const float4*)&g_keys[row*1024];

    float bd[KNN]; int bj[KNN];
    #pragma unroll
    for (int k=0;k<KNN;k++){ bd[k]=FLT_MAX; bj[k]=row & 1023; }
    float worst = FLT_MAX; int wpos = 0;

    auto ins = [&](float d, int j){
        if (d < worst){
            bd[wpos]=d; bj[wpos]=j;
            worst = bd[0]; wpos = 0;
            #pragma unroll
            for (int k=1;k<KNN;k++) if (bd[k] > worst){ worst = bd[k]; wpos = k; }
        }
    };

    for (int c = s; c < 256; c += 4){
        float4 v = krow[c];
        int j0 = c*4;
        ins(v.x, j0); ins(v.y, j0+1); ins(v.z, j0+2); ins(v.w, j0+3);
    }

    int cb = rl*80, off = s*20;
    #pragma unroll
    for (int k=0;k<KNN;k++) mk[cb+off+k] = bd[k];
    __syncthreads();
    #pragma unroll
    for (int k=0;k<KNN;k++){
        float kc = bd[k]; int cpos = off + k;
        int rank = 0;
        for (int q=0;q<80;q++){
            float kq = mk[cb+q];
            rank += (kq < kc) || (kq == kc && q < cpos);
        }
        if (rank < KNN) outIdx[row*KNN+rank] = jbase + bj[k];
    }
}

// ---------------- kernel 2: EdgeConv1 — transposed H + packed f32x2 layer2 ----
// dyn smem (floats): sW1f[384] | sb1f[64] | sb2[64] | sW2[4096] | Ht[8][64*36]
#define HT_STR 36
__global__ __launch_bounds__(256) void conv1_kernel(
    const float* __restrict__ pos,
    const float* __restrict__ W1, const float* __restrict__ b1,
    const float* __restrict__ bns, const float* __restrict__ bnb,
    const float* __restrict__ W2, const float* __restrict__ b2)
{
    extern __shared__ float smc[];
    float* sW1f = smc;            // 384
    float* sb1f = smc + 384;      // 64
    float* sb2  = smc + 448;      // 64
    float* sW2  = smc + 512;      // 4096
    float* sHt  = smc + 4608;     // 8 * 64*HT_STR

    int tid = threadIdx.x;
    for (int t = tid; t < 64; t += 256){
        float sc = bns[t];
        sb1f[t] = b1[t]*sc + bnb[t];    // fold BN into layer-1 affine
        sb2[t]  = b2[t];
        #pragma unroll
        for (int d=0; d<6; d++) sW1f[d*64+t] = W1[d*64+t]*sc;
    }
    for (int t = tid; t < 4096; t += 256) sW2[t] = W2[t];
    __syncthreads();

    int warp = tid >> 5, lane = tid & 31;
    int i = blockIdx.x*8 + warp;
    float xi0 = pos[i*3+0], xi1 = pos[i*3+1], xi2 = pos[i*3+2];
    float* Ht = sHt + warp*(64*HT_STR);   // Ht[k][j], row stride HT_STR
    int c0 = lane, c1 = lane + 32;

    float w3a = sW1f[192+c0], w4a = sW1f[256+c0], w5a = sW1f[320+c0];
    float w3b = sW1f[192+c1], w4b = sW1f[256+c1], w5b = sW1f[320+c1];
    float basea = sb1f[c0] + xi0*sW1f[c0] + xi1*sW1f[64+c0] + xi2*sW1f[128+c0];
    float baseb = sb1f[c1] + xi0*sW1f[c1] + xi1*sW1f[64+c1] + xi2*sW1f[128+c1];

    // layer 1: per-edge hidden, relu; store TRANSPOSED Ht[k][j] (k = own column)
    #pragma unroll
    for (int j4=0; j4<5; j4++){
        float h0[4], h1[4];
        #pragma unroll
        for (int jj=0; jj<4; jj++){
            int j = j4*4 + jj;
            int n = g_idx1[i*KNN+j];
            float d0 = pos[n*3+0]-xi0, d1 = pos[n*3+1]-xi1, d2 = pos[n*3+2]-xi2;
            h0[jj] = fmaxf(basea + d0*w3a + d1*w4a + d2*w5a, 0.f);
            h1[jj] = fmaxf(baseb + d0*w3b + d1*w4b + d2*w5b, 0.f);
        }
        *(float4*)&Ht[c0*HT_STR + j4*4] = make_float4(h0[0],h0[1],h0[2],h0[3]);
        *(float4*)&Ht[c1*HT_STR + j4*4] = make_float4(h1[0],h1[1],h1[2],h1[3]);
    }
    __syncwarp();

    // layer 2: packed f32x2 over j-pairs; weight scalar dup reused across 10 pairs
    float2 acc0[10], acc1[10];
    #pragma unroll
    for (int p=0;p<10;p++){ acc0[p]=make_float2(0.f,0.f); acc1[p]=make_float2(0.f,0.f); }
    #pragma unroll 4
    for (int k=0;k<64;k++){
        float w0 = sW2[k*64+c0];
        float w1 = sW2[k*64+c1];
        float2 w0d = make_float2(w0,w0);
        float2 w1d = make_float2(w1,w1);
        const float4* hr = (const float4*)&Ht[k*HT_STR];
        #pragma unroll
        for (int g=0; g<5; g++){
            float4 h = hr[g];                      // broadcast LDS.128
            float2 p0 = make_float2(h.x,h.y);
            float2 p1 = make_float2(h.z,h.w);
            acc0[g*2]   = ffma2(p0, w0d, acc0[g*2]);
            acc0[g*2+1] = ffma2(p1, w0d, acc0[g*2+1]);
            acc1[g*2]   = ffma2(p0, w1d, acc1[g*2]);
            acc1[g*2+1] = ffma2(p1, w1d, acc1[g*2+1]);
        }
    }
    float m0 = -FLT_MAX, m1 = -FLT_MAX;
    #pragma unroll
    for (int p=0;p<10;p++){
        m0 = fmaxf(m0, fmaxf(acc0[p].x, acc0[p].y));
        m1 = fmaxf(m1, fmaxf(acc1[p].x, acc1[p].y));
    }
    m0 += sb2[c0];
    m1 += sb2[c1];
    g_x1[i*64+c0] = m0;
    g_x1[i*64+c1] = m1;
    float sq = m0*m0 + m1*m1;
    #pragma unroll
    for (int o=16;o;o>>=1) sq += __shfl_xor_sync(0xffffffffu, sq, o);
    if (lane == 0) g_x1sq[i] = sq;
}

// ---------------- kernel 4: z = x1@Wb, s = x1@(Wt-Wb)+b ----------------
__global__ __launch_bounds__(256) void zs_kernel(const float* __restrict__ c2W,
                                                 const float* __restrict__ c2b){
    extern __shared__ float sm4[];
    float* sW = sm4;            // 128*128
    float* sx = sm4 + 16384;    // 8 warps * 2 pts * 64
    int tid = threadIdx.x, warp = tid>>5, lane = tid&31;
    for (int t=tid; t<16384; t+=256) sW[t] = c2W[t];
    __syncthreads();
    float cbv[4];
    #pragma unroll
    for (int q=0;q<4;q++) cbv[q] = c2b[lane+32*q];

    for (int g = blockIdx.x; g < NPTS/16; g += gridDim.x){
        int i0 = g*16 + warp*2;
        float* xw = sx + warp*128;
        xw[lane]      = g_x1[i0*64 + lane];
        xw[lane+32]   = g_x1[i0*64 + 32 + lane];
        xw[64+lane]   = g_x1[(i0+1)*64 + lane];
        xw[96+lane]   = g_x1[(i0+1)*64 + 32 + lane];
        __syncwarp();
        float az0[4]={0,0,0,0}, az1[4]={0,0,0,0}, at0[4]={0,0,0,0}, at1[4]={0,0,0,0};
        for (int k=0;k<64;k++){
            float x0 = xw[k], x1v = xw[64+k];
            #pragma unroll
            for (int q=0;q<4;q++){
                int c = lane + 32*q;
                float wt = sW[k*128+c];
                float wb = sW[(k+64)*128+c];
                at0[q] += x0*wt;  az0[q] += x0*wb;
                at1[q] += x1v*wt; az1[q] += x1v*wb;
            }
        }
        #pragma unroll
        for (int q=0;q<4;q++){
            int c = lane + 32*q;
            g_z[i0*128+c]     = az0[q];
            g_s[i0*128+c]     = at0[q]-az0[q]+cbv[q];
            g_z[(i0+1)*128+c] = az1[q];
            g_s[(i0+1)*128+c] = at1[q]-az1[q]+cbv[q];
        }
        __syncwarp();
    }
}

// ---------------- kernel 5: gather-max -> x2 ----------------
__global__ __launch_bounds__(256) void gather_kernel(){
    int gw   = (blockIdx.x*blockDim.x + threadIdx.x) >> 5;
    int lane = threadIdx.x & 31;
    if (gw >= NPTS) return;
    const int* idx = &g_idx2[gw*KNN];
    float4 m = make_float4(-FLT_MAX,-FLT_MAX,-FLT_MAX,-FLT_MAX);
    #pragma unroll
    for (int j=0;j<KNN;j++){
        int n = idx[j];
        float4 v = *(const float4*)&g_z[n*128 + lane*4];
        m.x = fmaxf(m.x, v.x); m.y = fmaxf(m.y, v.y);
        m.z = fmaxf(m.z, v.z); m.w = fmaxf(m.w, v.w);
    }
    float4 sv = *(const float4*)&g_s[gw*128 + lane*4];
    float4 r  = make_float4(sv.x+m.x, sv.y+m.y, sv.z+m.z, sv.w+m.w);
    *(float4*)&g_x2[gw*128 + lane*4] = r;
}

// ---------------- kernel 6: lin([x1,x2]) + global max pool ----------------
__global__ __launch_bounds__(512) void linpool_kernel(const float* __restrict__ lW,
                                                      const float* __restrict__ lb,
                                                      unsigned* __restrict__ out){
    extern __shared__ float sm6[];
    float* sW = sm6;              // 192*128
    float* sx = sm6 + 192*128;    // 16 warps * 4 pts * 192
    int tid = threadIdx.x, warp = tid>>5, lane = tid&31;
    for (int t=tid; t<192*128; t+=512) sW[t] = lW[t];
    __syncthreads();
    float lbv[4];
    #pragma unroll
    for (int q=0;q<4;q++) lbv[q] = lb[lane+32*q];

    for (int ch = blockIdx.x*16 + warp; ch < NPTS/4; ch += gridDim.x*16){
        int p0 = ch*4;
        float* xw = sx + warp*4*192;
        #pragma unroll
        for (int pt=0; pt<4; pt++){
            int p = p0 + pt;
            #pragma unroll
            for (int t6=0; t6<6; t6++){
                int t = lane + t6*32;
                xw[pt*192 + t] = (t < 64) ? g_x1[p*64 + t] : g_x2[p*128 + (t-64)];
            }
        }
        __syncwarp();
        float acc[4][4];
        #pragma unroll
        for (int pt=0;pt<4;pt++)
            #pragma unroll
            for (int q=0;q<4;q++) acc[pt][q] = 0.f;
        #pragma unroll 4
        for (int k=0;k<192;k++){
            float w0 = sW[k*128+lane],    w1 = sW[k*128+lane+32];
            float w2 = sW[k*128+lane+64], w3 = sW[k*128+lane+96];
            #pragma unroll
            for (int pt=0;pt<4;pt++){
                float xv = xw[pt*192+k];
                acc[pt][0] += xv*w0; acc[pt][1] += xv*w1;
                acc[pt][2] += xv*w2; acc[pt][3] += xv*w3;
            }
        }
        int cloud = p0 >> 10;
        #pragma unroll
        for (int q=0;q<4;q++){
            float m = fmaxf(fmaxf(acc[0][q],acc[1][q]), fmaxf(acc[2][q],acc[3][q])) + lbv[q];
            atomicMax(&out[cloud*128 + lane + 32*q], f2key(m));
        }
        __syncwarp();
    }
}

// ---------------- launch ----------------
extern "C" void kernel_launch(void* const* d_in, const int* in_sizes, int n_in,
                              void* d_out, int out_size)
{
    const float* pos  = (const float*)d_in[0];
    const float* c1W1 = (const float*)d_in[2];
    const float* c1b1 = (const float*)d_in[3];
    const float* bns  = (const float*)d_in[4];
    const float* bnb  = (const float*)d_in[5];
    const float* c1W2 = (const float*)d_in[6];
    const float* c1b2 = (const float*)d_in[7];
    const float* c2W  = (const float*)d_in[8];
    const float* c2b  = (const float*)d_in[9];
    const float* lW   = (const float*)d_in[10];
    const float* lb   = (const float*)d_in[11];
    unsigned* out = (unsigned*)d_out;

    int* d_idx1; cudaGetSymbolAddress((void**)&d_idx1, g_idx1);
    int* d_idx2; cudaGetSymbolAddress((void**)&d_idx2, g_idx2);

    const int C1_SMEM = (4608 + 8*64*HT_STR) * 4;          // 92,160 B
    const int FK_SMEM = (8192*2 + 128) * 4;                // 66,048 B
    const int ZS_SMEM = (16384 + 8*128) * 4;               // 69,632 B
    const int LP_SMEM = (192*128 + 16*4*192) * 4;          // 147,456 B
    cudaFuncSetAttribute(conv1_kernel,     cudaFuncAttributeMaxDynamicSharedMemorySize, C1_SMEM);
    cudaFuncSetAttribute(feat_keys_kernel, cudaFuncAttributeMaxDynamicSharedMemorySize, FK_SMEM);
    cudaFuncSetAttribute(zs_kernel,        cudaFuncAttributeMaxDynamicSharedMemorySize, ZS_SMEM);
    cudaFuncSetAttribute(linpool_kernel,   cudaFuncAttributeMaxDynamicSharedMemorySize, LP_SMEM);

    init_out_kernel<<<16, 256>>>(out);
    dist_pos_kernel<<<dim3(8,8,BATCH), 256>>>(pos);
    select_kernel<<<NPTS/64, 256>>>(d_idx1);
    conv1_kernel<<<NPTS/8, 256, C1_SMEM>>>(pos, c1W1, c1b1, bns, bnb, c1W2, c1b2);
    feat_keys_kernel<<<dim3(8,8,BATCH), 512, FK_SMEM>>>();
    select_kernel<<<NPTS/64, 256>>>(d_idx2);
    zs_kernel<<<444, 256, ZS_SMEM>>>(c2W, c2b);
    gather_kernel<<<NPTS/8, 256>>>();
    linpool_kernel<<<148, 512, LP_SMEM>>>(lW, lb, out);
    decode_out_kernel<<<16, 256>>>(out);
}